// round 6
// baseline (speedup 1.0000x reference)
#include <cuda_runtime.h>
#include <cstdint>

#define BB 64
#define TT 512
#define HH 512
#define EE 256
#define G4 2048          // 4*H
#define NCTA 128         // persistent CTAs in scan (<= 148 SMs, all co-resident)
#define PH  516          // hs row pitch in floats: 2064B = 16B-aligned, 516 mod 32 = 4

// ---------------- device scratch (static: no allocations allowed) ----------------
__device__ float    g_gates[(size_t)TT * BB * G4];  // 256 MB: gates_x, layout [t][b][j][gate]
__device__ float    g_h[2][BB * HH];                // double-buffered carry h (post-reset)
__device__ unsigned g_bar[TT];                      // per-step barrier counters (zeroed by gates)

// ---------------- small asm helpers ----------------------------------------------
__device__ __forceinline__ unsigned long long pk2(float lo, float hi) {
    unsigned long long r;
    asm("mov.b64 %0, {%1,%2};" : "=l"(r) : "f"(lo), "f"(hi));
    return r;
}
__device__ __forceinline__ float2 upk2(unsigned long long v) {
    float2 r;
    asm("mov.b64 {%0,%1}, %2;" : "=f"(r.x), "=f"(r.y) : "l"(v));
    return r;
}
#define FFMA2(acc, a, b) \
    asm("fma.rn.f32x2 %0, %1, %2, %0;" : "+l"(acc) : "l"(a), "l"(b))

__device__ __forceinline__ unsigned smem_u32(const void* p) {
    return (unsigned)__cvta_generic_to_shared(p);
}
__device__ __forceinline__ unsigned long long lds_b64(unsigned addr) {
    unsigned long long r;
    asm("ld.shared.b64 %0, [%1];" : "=l"(r) : "r"(addr));
    return r;
}
__device__ __forceinline__ void lds_v2u64(unsigned addr, unsigned long long& a,
                                          unsigned long long& b) {
    asm("ld.shared.v2.u64 {%0,%1}, [%2];" : "=l"(a), "=l"(b) : "r"(addr));
}
__device__ __forceinline__ void sts_v4f32(unsigned addr, float4 v) {
    asm volatile("st.shared.v4.f32 [%0], {%1,%2,%3,%4};"
                 :: "r"(addr), "f"(v.x), "f"(v.y), "f"(v.z), "f"(v.w));
}
__device__ __forceinline__ unsigned atom_add_release_gpu(unsigned* p, unsigned v) {
    unsigned old;
    asm volatile("atom.release.gpu.global.add.u32 %0, [%1], %2;"
                 : "=r"(old) : "l"(p), "r"(v) : "memory");
    return old;
}
__device__ __forceinline__ unsigned ld_acquire_gpu(const unsigned* p) {
    unsigned v;
    asm volatile("ld.acquire.gpu.global.u32 %0, [%1];" : "=r"(v) : "l"(p) : "memory");
    return v;
}

// ---------------- gates_x GEMM with fused embedding gather -----------------------
// Also does per-launch init in nb==0 blocks: out_mask row for its t + g_bar[t]=0.
__global__ __launch_bounds__(256) void gates_kernel(const int* __restrict__ inputs,
                                                    const float* __restrict__ emb,
                                                    const float* __restrict__ Wih,
                                                    const float* __restrict__ bih,
                                                    const float* __restrict__ bhh,
                                                    const int* __restrict__ lengths,
                                                    float* __restrict__ out_mask) {
    __shared__ float As[64 * 69];   // [b][k] pitch 69
    __shared__ float Bs[64 * 69];   // [n][k] pitch 69
    __shared__ int   tok[64];
    __shared__ float bias_s[64];

    const int t   = blockIdx.y;
    const int nb  = blockIdx.x;
    const int tid = threadIdx.x;
    const int tx  = tid & 15;
    const int ty  = tid >> 4;

    if (nb == 0) {
        if (tid < 64) {
            out_mask[tid * TT + t] = (t < lengths[tid]) ? 1.f : 0.f;
        } else if (tid == 64) {
            g_bar[t] = 0u;     // reset scan barrier for this launch (stream-ordered)
        }
    }

    if (tid < 64) {
        tok[tid] = inputs[tid * TT + t];
    } else if (tid < 128) {
        int n  = nb * 64 + (tid - 64);
        int wr = (n & 3) * 512 + (n >> 2);
        bias_s[tid - 64] = bih[wr] + bhh[wr];
    }
    __syncthreads();

    float acc[4][4] = {};
    for (int kc = 0; kc < EE; kc += 64) {
#pragma unroll
        for (int i = 0; i < 16; i++) {
            int idx = i * 256 + tid;
            int mi  = idx >> 6;
            int kk  = idx & 63;
            As[mi * 69 + kk] = emb[(size_t)tok[mi] * EE + kc + kk];
            int n  = nb * 64 + mi;
            int wr = (n & 3) * 512 + (n >> 2);
            Bs[mi * 69 + kk] = Wih[wr * EE + kc + kk];
        }
        __syncthreads();
#pragma unroll 8
        for (int kk = 0; kk < 64; kk++) {
            float a0 = As[(ty * 4 + 0) * 69 + kk];
            float a1 = As[(ty * 4 + 1) * 69 + kk];
            float a2 = As[(ty * 4 + 2) * 69 + kk];
            float a3 = As[(ty * 4 + 3) * 69 + kk];
            float b0 = Bs[(tx * 4 + 0) * 69 + kk];
            float b1 = Bs[(tx * 4 + 1) * 69 + kk];
            float b2 = Bs[(tx * 4 + 2) * 69 + kk];
            float b3 = Bs[(tx * 4 + 3) * 69 + kk];
            acc[0][0] = fmaf(a0, b0, acc[0][0]);
            acc[0][1] = fmaf(a0, b1, acc[0][1]);
            acc[0][2] = fmaf(a0, b2, acc[0][2]);
            acc[0][3] = fmaf(a0, b3, acc[0][3]);
            acc[1][0] = fmaf(a1, b0, acc[1][0]);
            acc[1][1] = fmaf(a1, b1, acc[1][1]);
            acc[1][2] = fmaf(a1, b2, acc[1][2]);
            acc[1][3] = fmaf(a1, b3, acc[1][3]);
            acc[2][0] = fmaf(a2, b0, acc[2][0]);
            acc[2][1] = fmaf(a2, b1, acc[2][1]);
            acc[2][2] = fmaf(a2, b2, acc[2][2]);
            acc[2][3] = fmaf(a2, b3, acc[2][3]);
            acc[3][0] = fmaf(a3, b0, acc[3][0]);
            acc[3][1] = fmaf(a3, b1, acc[3][1]);
            acc[3][2] = fmaf(a3, b2, acc[3][2]);
            acc[3][3] = fmaf(a3, b3, acc[3][3]);
        }
        __syncthreads();
    }

    float* gp = g_gates + (size_t)(t * 64) * G4 + nb * 64;
#pragma unroll
    for (int r = 0; r < 4; r++) {
        float4 v;
        v.x = acc[r][0] + bias_s[tx * 4 + 0];
        v.y = acc[r][1] + bias_s[tx * 4 + 1];
        v.z = acc[r][2] + bias_s[tx * 4 + 2];
        v.w = acc[r][3] + bias_s[tx * 4 + 3];
        *reinterpret_cast<float4*>(gp + (size_t)(ty * 4 + r) * G4 + tx * 4) = v;
    }
}

// ---------------- persistent LSTM scan -------------------------------------------
// CTA owns j in [cta*4, cta*4+4). Thread: b = tid>>2, jl = tid&3.
// t=0 skips the h staging/GEMV entirely (h == 0), so g_h needs no init.
// Grid barrier = CG pattern: bar.sync; tid0 atom.release.gpu.add; poll ld.acquire.
// Critical-path hiding: arrive FIRST, then store d_out + prefetch gx(t+1)/reset(t+1),
// THEN poll.
__global__ __launch_bounds__(256, 1) void scan_kernel(const float* __restrict__ Whh,
                                                      const int* __restrict__ lengths,
                                                      const int* __restrict__ resets,
                                                      float* __restrict__ d_out) {
    extern __shared__ float sm[];
    float* Wp = sm;                 // 256*4*4*2 = 8192 floats (32 KB)
    float* hs = sm + 8192;          // 64 * 516  = 33024 floats (129 KB)

    const int tid = threadIdx.x;
    const int b   = tid >> 2;      // 0..63
    const int jl  = tid & 3;       // 0..3
    const int j   = blockIdx.x * 4 + jl;

    // stage Wp: idx = p*32 + jl_*8 + g*2 + par  ->  Whh[(g*512 + j0+jl_)*512 + 2p+par]
    for (int idx = tid; idx < 8192; idx += 256) {
        int par = idx & 1;
        int g   = (idx >> 1) & 3;
        int jj  = (idx >> 3) & 3;
        int p   = idx >> 5;
        Wp[idx] = Whh[((size_t)(g * 512 + blockIdx.x * 4 + jj)) * 512 + 2 * p + par];
    }

    float c_reg = 0.f;
    const int len_b = lengths[b];

    const float4* gx4 = reinterpret_cast<const float4*>(g_gates);
    float* hT = d_out + (size_t)BB * TT * HH;
    float* cT = hT + BB * HH;

    const unsigned hs_s  = smem_u32(hs);
    const unsigned wp_s  = smem_u32(Wp);
    const unsigned hrow  = hs_s + (unsigned)(b * PH) * 4u;
    const unsigned wbase = wp_s + (unsigned)(jl * 8) * 4u;

    // prefetch step 0 operands
    float4 gx = __ldg(&gx4[(size_t)(0 * BB + b) * 512 + j]);
    int    rv = __ldg(&resets[b * TT + 0]);

    __syncthreads();

    for (int t = 0; t < TT; t++) {
        const float4* gh4 = reinterpret_cast<const float4*>(g_h[t & 1]);
        float*        ghw = g_h[(t + 1) & 1];

        unsigned long long acc0 = pk2(gx.x, 0.f);
        unsigned long long acc1 = pk2(gx.y, 0.f);
        unsigned long long acc2 = pk2(gx.z, 0.f);
        unsigned long long acc3 = pk2(gx.w, 0.f);

        float h_prev = 0.f;
        if (t > 0) {
            // ---- stage chunk 0 ----
#pragma unroll
            for (int i = 0; i < 8; i++) {
                int idx = i * 256 + tid;
                int b2  = idx >> 5;
                int q   = idx & 31;
                float4 v = __ldcg(&gh4[b2 * 128 + q]);
                sts_v4f32(hs_s + (unsigned)(b2 * PH + q * 4) * 4u, v);
            }
            __syncthreads();

#pragma unroll
            for (int c = 0; c < 4; c++) {
                if (c < 3) {
#pragma unroll
                    for (int i = 0; i < 8; i++) {
                        int idx = i * 256 + tid;
                        int b2  = idx >> 5;
                        int q   = idx & 31;
                        float4 v = __ldcg(&gh4[b2 * 128 + (c + 1) * 32 + q]);
                        sts_v4f32(hs_s + (unsigned)(b2 * PH + ((c + 1) * 32 + q) * 4) * 4u, v);
                    }
                }
#pragma unroll 16
                for (int p = c * 64; p < c * 64 + 64; p++) {
                    unsigned long long h2 = lds_b64(hrow + (unsigned)(2 * p) * 4u);
                    unsigned long long w0, w1, w2, w3;
                    unsigned wa = wbase + (unsigned)(p * 32) * 4u;
                    lds_v2u64(wa,       w0, w1);
                    lds_v2u64(wa + 16u, w2, w3);
                    FFMA2(acc0, h2, w0);
                    FFMA2(acc1, h2, w1);
                    FFMA2(acc2, h2, w2);
                    FFMA2(acc3, h2, w3);
                }
                __syncthreads();
            }
            h_prev = hs[b * PH + j];
        }

        // ---- reduce halves, activations, state update ----
        float2 r0 = upk2(acc0), r1 = upk2(acc1), r2 = upk2(acc2), r3 = upk2(acc3);
        float si = r0.x + r0.y;
        float sf = r1.x + r1.y;
        float sg = r2.x + r2.y;
        float so = r3.x + r3.y;

        float ig = 1.f / (1.f + __expf(-si));
        float fg = 1.f / (1.f + __expf(-sf));
        float gg = tanhf(sg);
        float og = 1.f / (1.f + __expf(-so));
        float c_new = fg * c_reg + ig * gg;
        float h_new = og * tanhf(c_new);

        float m  = (t < len_b) ? 1.f : 0.f;
        float h_nx = m * h_new + (1.f - m) * h_prev;
        float c_nx = m * c_new + (1.f - m) * c_reg;

        float rr = (float)rv;
        c_reg = c_nx * (1.f - rr);
        float h_carry = h_nx * (1.f - rr);
        ghw[b * HH + j] = h_carry;     // publish BEFORE barrier

        if (t < TT - 1) {
            __syncthreads();                                   // CTA writes done
            if (tid == 0) atom_add_release_gpu(&g_bar[t], 1u); // arrive (cumulative release)

            // useful work inside the barrier window:
            d_out[((size_t)b * TT + t) * HH + j] = h_nx;
            gx = __ldg(&gx4[(size_t)((t + 1) * BB + b) * 512 + j]);
            rv = __ldg(&resets[b * TT + t + 1]);

            if (tid == 0) {
                while (ld_acquire_gpu(&g_bar[t]) < (unsigned)NCTA) { }
            }
            __syncthreads();
        } else {
            d_out[((size_t)b * TT + t) * HH + j] = h_nx;
            hT[b * HH + j] = h_carry;
            cT[b * HH + j] = c_reg;
        }
    }
}

// ---------------- launch ---------------------------------------------------------
extern "C" void kernel_launch(void* const* d_in, const int* in_sizes, int n_in,
                              void* d_out, int out_size) {
    const int*   inputs  = (const int*)d_in[0];
    const int*   lengths = (const int*)d_in[1];
    const int*   resets  = (const int*)d_in[2];
    const float* emb     = (const float*)d_in[3];
    const float* Wih     = (const float*)d_in[4];
    const float* Whh     = (const float*)d_in[5];
    const float* bih     = (const float*)d_in[6];
    const float* bhh     = (const float*)d_in[7];
    float* out = (float*)d_out;
    float* out_mask = out + (size_t)BB * TT * HH + 2 * (size_t)BB * HH;

    const int SMEM_SCAN = (8192 + 64 * PH) * (int)sizeof(float);  // 164864 B
    cudaFuncSetAttribute(scan_kernel, cudaFuncAttributeMaxDynamicSharedMemorySize, SMEM_SCAN);

    gates_kernel<<<dim3(32, 512), 256>>>(inputs, emb, Wih, bih, bhh, lengths, out_mask);
    scan_kernel<<<NCTA, 256, SMEM_SCAN>>>(Whh, lengths, resets, out);
}

// round 7
// speedup vs baseline: 1.0114x; 1.0114x over previous
#include <cuda_runtime.h>
#include <cstdint>

#define BB 64
#define TT 512
#define HH 512
#define EE 256
#define G4 2048          // 4*H
#define NCTA 128         // persistent CTAs in scan (<= 148 SMs, all co-resident)
#define PH  516          // hs row pitch in floats: 2064B = 16B-aligned, 516 mod 32 = 4

// ---------------- device scratch (static: no allocations allowed) ----------------
__device__ float    g_gates[(size_t)TT * BB * G4];  // 256 MB: gates_x, layout [t][b][j][gate]
__device__ float    g_h[2][BB * HH];                // double-buffered carry h (post-reset)
__device__ unsigned g_bar[TT];                      // per-step arrive counters
__device__ unsigned g_go[TT];                       // per-step go flags (set once)

// ---------------- small asm helpers ----------------------------------------------
__device__ __forceinline__ unsigned long long pk2(float lo, float hi) {
    unsigned long long r;
    asm("mov.b64 %0, {%1,%2};" : "=l"(r) : "f"(lo), "f"(hi));
    return r;
}
__device__ __forceinline__ float2 upk2(unsigned long long v) {
    float2 r;
    asm("mov.b64 {%0,%1}, %2;" : "=f"(r.x), "=f"(r.y) : "l"(v));
    return r;
}
#define FFMA2(acc, a, b) \
    asm("fma.rn.f32x2 %0, %1, %2, %0;" : "+l"(acc) : "l"(a), "l"(b))

__device__ __forceinline__ unsigned smem_u32(const void* p) {
    return (unsigned)__cvta_generic_to_shared(p);
}
__device__ __forceinline__ unsigned long long lds_b64(unsigned addr) {
    unsigned long long r;
    asm("ld.shared.b64 %0, [%1];" : "=l"(r) : "r"(addr));
    return r;
}
__device__ __forceinline__ void lds_v2u64(unsigned addr, unsigned long long& a,
                                          unsigned long long& b) {
    asm("ld.shared.v2.u64 {%0,%1}, [%2];" : "=l"(a), "=l"(b) : "r"(addr));
}
__device__ __forceinline__ void sts_v4f32(unsigned addr, float4 v) {
    asm volatile("st.shared.v4.f32 [%0], {%1,%2,%3,%4};"
                 :: "r"(addr), "f"(v.x), "f"(v.y), "f"(v.z), "f"(v.w));
}
__device__ __forceinline__ unsigned atom_acqrel_add_gpu(unsigned* p, unsigned v) {
    unsigned old;
    asm volatile("atom.acq_rel.gpu.global.add.u32 %0, [%1], %2;"
                 : "=r"(old) : "l"(p), "r"(v) : "memory");
    return old;
}
__device__ __forceinline__ void st_release_gpu(unsigned* p, unsigned v) {
    asm volatile("st.release.gpu.global.u32 [%0], %1;" :: "l"(p), "r"(v) : "memory");
}
__device__ __forceinline__ unsigned ld_acquire_gpu(const unsigned* p) {
    unsigned v;
    asm volatile("ld.acquire.gpu.global.u32 %0, [%1];" : "=r"(v) : "l"(p) : "memory");
    return v;
}

// ---------------- gates_x GEMM with fused embedding gather -----------------------
// Also per-launch init in nb==0 blocks: out_mask row for its t, g_bar[t]=g_go[t]=0.
__global__ __launch_bounds__(256) void gates_kernel(const int* __restrict__ inputs,
                                                    const float* __restrict__ emb,
                                                    const float* __restrict__ Wih,
                                                    const float* __restrict__ bih,
                                                    const float* __restrict__ bhh,
                                                    const int* __restrict__ lengths,
                                                    float* __restrict__ out_mask) {
    __shared__ float As[64 * 69];   // [b][k] pitch 69
    __shared__ float Bs[64 * 69];   // [n][k] pitch 69
    __shared__ int   tok[64];
    __shared__ float bias_s[64];

    const int t   = blockIdx.y;
    const int nb  = blockIdx.x;
    const int tid = threadIdx.x;
    const int tx  = tid & 15;
    const int ty  = tid >> 4;

    if (nb == 0) {
        if (tid < 64) {
            out_mask[tid * TT + t] = (t < lengths[tid]) ? 1.f : 0.f;
        } else if (tid == 64) {
            g_bar[t] = 0u;
            g_go[t]  = 0u;
        }
    }

    if (tid < 64) {
        tok[tid] = inputs[tid * TT + t];
    } else if (tid < 128) {
        int n  = nb * 64 + (tid - 64);
        int wr = (n & 3) * 512 + (n >> 2);
        bias_s[tid - 64] = bih[wr] + bhh[wr];
    }
    __syncthreads();

    float acc[4][4] = {};
    for (int kc = 0; kc < EE; kc += 64) {
#pragma unroll
        for (int i = 0; i < 16; i++) {
            int idx = i * 256 + tid;
            int mi  = idx >> 6;
            int kk  = idx & 63;
            As[mi * 69 + kk] = emb[(size_t)tok[mi] * EE + kc + kk];
            int n  = nb * 64 + mi;
            int wr = (n & 3) * 512 + (n >> 2);
            Bs[mi * 69 + kk] = Wih[wr * EE + kc + kk];
        }
        __syncthreads();
#pragma unroll 8
        for (int kk = 0; kk < 64; kk++) {
            float a0 = As[(ty * 4 + 0) * 69 + kk];
            float a1 = As[(ty * 4 + 1) * 69 + kk];
            float a2 = As[(ty * 4 + 2) * 69 + kk];
            float a3 = As[(ty * 4 + 3) * 69 + kk];
            float b0 = Bs[(tx * 4 + 0) * 69 + kk];
            float b1 = Bs[(tx * 4 + 1) * 69 + kk];
            float b2 = Bs[(tx * 4 + 2) * 69 + kk];
            float b3 = Bs[(tx * 4 + 3) * 69 + kk];
            acc[0][0] = fmaf(a0, b0, acc[0][0]);
            acc[0][1] = fmaf(a0, b1, acc[0][1]);
            acc[0][2] = fmaf(a0, b2, acc[0][2]);
            acc[0][3] = fmaf(a0, b3, acc[0][3]);
            acc[1][0] = fmaf(a1, b0, acc[1][0]);
            acc[1][1] = fmaf(a1, b1, acc[1][1]);
            acc[1][2] = fmaf(a1, b2, acc[1][2]);
            acc[1][3] = fmaf(a1, b3, acc[1][3]);
            acc[2][0] = fmaf(a2, b0, acc[2][0]);
            acc[2][1] = fmaf(a2, b1, acc[2][1]);
            acc[2][2] = fmaf(a2, b2, acc[2][2]);
            acc[2][3] = fmaf(a2, b3, acc[2][3]);
            acc[3][0] = fmaf(a3, b0, acc[3][0]);
            acc[3][1] = fmaf(a3, b1, acc[3][1]);
            acc[3][2] = fmaf(a3, b2, acc[3][2]);
            acc[3][3] = fmaf(a3, b3, acc[3][3]);
        }
        __syncthreads();
    }

    float* gp = g_gates + (size_t)(t * 64) * G4 + nb * 64;
#pragma unroll
    for (int r = 0; r < 4; r++) {
        float4 v;
        v.x = acc[r][0] + bias_s[tx * 4 + 0];
        v.y = acc[r][1] + bias_s[tx * 4 + 1];
        v.z = acc[r][2] + bias_s[tx * 4 + 2];
        v.w = acc[r][3] + bias_s[tx * 4 + 3];
        *reinterpret_cast<float4*>(gp + (size_t)(ty * 4 + r) * G4 + tx * 4) = v;
    }
}

// ---------------- persistent LSTM scan (512 thr, k-split lanes, go-flag barrier) --
// pair = tid>>1 owns (b = pair>>2, jl = pair&3); half = tid&1 takes p = 2q+half
// (p = k-pair index), q in [0,128). Lane pairs reduce via shfl.xor(1); even lane
// stores. 16 warps/SM for latency hiding. Barrier: atom.acq_rel arrive; last
// arriver st.release's g_go[t]; others poll ld.acquire with nanosleep backoff.
__global__ __launch_bounds__(512, 1) void scan_kernel(const float* __restrict__ Whh,
                                                      const int* __restrict__ lengths,
                                                      const int* __restrict__ resets,
                                                      float* __restrict__ d_out) {
    extern __shared__ float sm[];
    float* Wp = sm;                 // 256 p * 32 floats = 8192 floats (32 KB)
    float* hs = sm + 8192;          // 64 * 516 = 33024 floats (129 KB)

    const int tid  = threadIdx.x;
    const int pair = tid >> 1;     // 0..255
    const int half = tid & 1;      // 0 / 1  (k-parity split)
    const int b    = pair >> 2;    // 0..63
    const int jl   = pair & 3;     // 0..3
    const int j    = blockIdx.x * 4 + jl;

    // stage Wp: idx = p*32 + jl_*8 + g*2 + par -> Whh[(g*512 + j0+jl_)*512 + 2p+par]
    for (int idx = tid; idx < 8192; idx += 512) {
        int par = idx & 1;
        int g   = (idx >> 1) & 3;
        int jj  = (idx >> 3) & 3;
        int p   = idx >> 5;
        Wp[idx] = Whh[((size_t)(g * 512 + blockIdx.x * 4 + jj)) * 512 + 2 * p + par];
    }

    float c_reg = 0.f;
    const int len_b = lengths[b];

    const float4* gx4 = reinterpret_cast<const float4*>(g_gates);
    float* hT = d_out + (size_t)BB * TT * HH;
    float* cT = hT + BB * HH;

    const unsigned hs_s  = smem_u32(hs);
    const unsigned wp_s  = smem_u32(Wp);
    const unsigned hrow  = hs_s + (unsigned)(b * PH) * 4u;
    const unsigned wbase = wp_s + (unsigned)(jl * 8) * 4u;

    // prefetch step 0 operands
    float4 gx = __ldg(&gx4[(size_t)(0 * BB + b) * 512 + j]);
    int    rv = __ldg(&resets[b * TT + 0]);

    __syncthreads();

    for (int t = 0; t < TT; t++) {
        const float4* gh4 = reinterpret_cast<const float4*>(g_h[t & 1]);
        float*        ghw = g_h[(t + 1) & 1];

        unsigned long long acc0 = pk2(half ? 0.f : gx.x, 0.f);
        unsigned long long acc1 = pk2(half ? 0.f : gx.y, 0.f);
        unsigned long long acc2 = pk2(half ? 0.f : gx.z, 0.f);
        unsigned long long acc3 = pk2(half ? 0.f : gx.w, 0.f);

        float h_prev = 0.f;
        if (t > 0) {
            // ---- stage chunk 0 (k 0..127) ----
#pragma unroll
            for (int i = 0; i < 4; i++) {
                int idx = i * 512 + tid;           // 0..2047
                int b2  = idx >> 5;
                int q4  = idx & 31;
                float4 v = __ldcg(&gh4[b2 * 128 + q4]);
                sts_v4f32(hs_s + (unsigned)(b2 * PH + q4 * 4) * 4u, v);
            }
            __syncthreads();

#pragma unroll
            for (int c = 0; c < 4; c++) {
                if (c < 3) {
#pragma unroll
                    for (int i = 0; i < 4; i++) {
                        int idx = i * 512 + tid;
                        int b2  = idx >> 5;
                        int q4  = idx & 31;
                        float4 v = __ldcg(&gh4[b2 * 128 + (c + 1) * 32 + q4]);
                        sts_v4f32(hs_s + (unsigned)(b2 * PH + ((c + 1) * 32 + q4) * 4) * 4u, v);
                    }
                }
                // GEMV over q in [c*32, c*32+32), p = 2q + half
#pragma unroll 16
                for (int q = c * 32; q < c * 32 + 32; q++) {
                    int p = 2 * q + half;
                    unsigned long long h2 = lds_b64(hrow + (unsigned)(p * 8));
                    unsigned long long w0, w1, w2, w3;
                    unsigned wa = wbase + (unsigned)(p * 128);
                    lds_v2u64(wa,       w0, w1);
                    lds_v2u64(wa + 16u, w2, w3);
                    FFMA2(acc0, h2, w0);
                    FFMA2(acc1, h2, w1);
                    FFMA2(acc2, h2, w2);
                    FFMA2(acc3, h2, w3);
                }
                __syncthreads();
            }
            h_prev = hs[b * PH + j];
        }

        // ---- reduce: f32x2 halves, then lane-pair butterfly ----
        float2 r0 = upk2(acc0), r1 = upk2(acc1), r2 = upk2(acc2), r3 = upk2(acc3);
        float si = r0.x + r0.y;
        float sf = r1.x + r1.y;
        float sg = r2.x + r2.y;
        float so = r3.x + r3.y;
        si += __shfl_xor_sync(0xFFFFFFFFu, si, 1);
        sf += __shfl_xor_sync(0xFFFFFFFFu, sf, 1);
        sg += __shfl_xor_sync(0xFFFFFFFFu, sg, 1);
        so += __shfl_xor_sync(0xFFFFFFFFu, so, 1);
        // odd lane contributed 0 to gx, even lane's gx included once; sums identical
        // in both lanes (commutative same-rounding adds).

        float ig = 1.f / (1.f + __expf(-si));
        float fg = 1.f / (1.f + __expf(-sf));
        float gg = tanhf(sg);
        float og = 1.f / (1.f + __expf(-so));
        float c_new = fg * c_reg + ig * gg;
        float h_new = og * tanhf(c_new);

        float m  = (t < len_b) ? 1.f : 0.f;
        float h_nx = m * h_new + (1.f - m) * h_prev;
        float c_nx = m * c_new + (1.f - m) * c_reg;

        float rr = (float)rv;
        c_reg = c_nx * (1.f - rr);
        float h_carry = h_nx * (1.f - rr);
        if (half == 0) ghw[b * HH + j] = h_carry;    // publish BEFORE barrier

        if (t < TT - 1) {
            __syncthreads();                          // CTA writes done
            bool last = false;
            if (tid == 0) {
                unsigned old = atom_acqrel_add_gpu(&g_bar[t], 1u);
                if (old == (unsigned)NCTA - 1u) {
                    st_release_gpu(&g_go[t], 1u);     // release everyone
                    last = true;
                }
            }
            // useful work inside the barrier window:
            if (half == 0) d_out[((size_t)b * TT + t) * HH + j] = h_nx;
            gx = __ldg(&gx4[(size_t)((t + 1) * BB + b) * 512 + j]);
            rv = __ldg(&resets[b * TT + t + 1]);

            if (tid == 0 && !last) {
                unsigned ns = 64;
                while (ld_acquire_gpu(&g_go[t]) == 0u) {
                    __nanosleep(ns);
                    if (ns < 512u) ns <<= 1;
                }
            }
            __syncthreads();
        } else {
            if (half == 0) {
                d_out[((size_t)b * TT + t) * HH + j] = h_nx;
                hT[b * HH + j] = h_carry;
                cT[b * HH + j] = c_reg;
            }
        }
    }
}

// ---------------- launch ---------------------------------------------------------
extern "C" void kernel_launch(void* const* d_in, const int* in_sizes, int n_in,
                              void* d_out, int out_size) {
    const int*   inputs  = (const int*)d_in[0];
    const int*   lengths = (const int*)d_in[1];
    const int*   resets  = (const int*)d_in[2];
    const float* emb     = (const float*)d_in[3];
    const float* Wih     = (const float*)d_in[4];
    const float* Whh     = (const float*)d_in[5];
    const float* bih     = (const float*)d_in[6];
    const float* bhh     = (const float*)d_in[7];
    float* out = (float*)d_out;
    float* out_mask = out + (size_t)BB * TT * HH + 2 * (size_t)BB * HH;

    const int SMEM_SCAN = (8192 + 64 * PH) * (int)sizeof(float);  // 164864 B
    cudaFuncSetAttribute(scan_kernel, cudaFuncAttributeMaxDynamicSharedMemorySize, SMEM_SCAN);

    gates_kernel<<<dim3(32, 512), 256>>>(inputs, emb, Wih, bih, bhh, lengths, out_mask);
    scan_kernel<<<NCTA, 512, SMEM_SCAN>>>(Whh, lengths, resets, out);
}

// round 8
// speedup vs baseline: 1.0280x; 1.0165x over previous
#include <cuda_runtime.h>
#include <cstdint>

#define BB 64
#define TT 512
#define HH 512
#define EE 256
#define G4 2048          // 4*H
#define NCTA 128         // persistent CTAs in scan (<= 148 SMs, all co-resident)
#define PH  516          // hs row pitch in floats: 2064B = 16B-aligned, 516 mod 32 = 4

// ---------------- device scratch (static: no allocations allowed) ----------------
__device__ float    g_gates[(size_t)TT * BB * G4];  // 256 MB: gates_x, layout [t][b][j][gate]
__device__ float    g_h[2][BB * HH];                // double-buffered carry h (post-reset)
__device__ unsigned g_bar[TT];                      // per-step arrive counters

// ---------------- small asm helpers ----------------------------------------------
__device__ __forceinline__ unsigned long long pk2(float lo, float hi) {
    unsigned long long r;
    asm("mov.b64 %0, {%1,%2};" : "=l"(r) : "f"(lo), "f"(hi));
    return r;
}
__device__ __forceinline__ float2 upk2(unsigned long long v) {
    float2 r;
    asm("mov.b64 {%0,%1}, %2;" : "=f"(r.x), "=f"(r.y) : "l"(v));
    return r;
}
#define FFMA2(acc, a, b) \
    asm("fma.rn.f32x2 %0, %1, %2, %0;" : "+l"(acc) : "l"(a), "l"(b))

__device__ __forceinline__ unsigned smem_u32(const void* p) {
    return (unsigned)__cvta_generic_to_shared(p);
}
__device__ __forceinline__ unsigned long long lds_b64(unsigned addr) {
    unsigned long long r;
    asm("ld.shared.b64 %0, [%1];" : "=l"(r) : "r"(addr));
    return r;
}
__device__ __forceinline__ void lds_v2u64(unsigned addr, unsigned long long& a,
                                          unsigned long long& b) {
    asm("ld.shared.v2.u64 {%0,%1}, [%2];" : "=l"(a), "=l"(b) : "r"(addr));
}
__device__ __forceinline__ void sts_v4f32(unsigned addr, float4 v) {
    asm volatile("st.shared.v4.f32 [%0], {%1,%2,%3,%4};"
                 :: "r"(addr), "f"(v.x), "f"(v.y), "f"(v.z), "f"(v.w));
}

// ---------------- gates_x GEMM with fused embedding gather -----------------------
// Also per-launch init in nb==0 blocks: out_mask row for its t, g_bar[t]=0.
__global__ __launch_bounds__(256) void gates_kernel(const int* __restrict__ inputs,
                                                    const float* __restrict__ emb,
                                                    const float* __restrict__ Wih,
                                                    const float* __restrict__ bih,
                                                    const float* __restrict__ bhh,
                                                    const int* __restrict__ lengths,
                                                    float* __restrict__ out_mask) {
    __shared__ float As[64 * 69];   // [b][k] pitch 69
    __shared__ float Bs[64 * 69];   // [n][k] pitch 69
    __shared__ int   tok[64];
    __shared__ float bias_s[64];

    const int t   = blockIdx.y;
    const int nb  = blockIdx.x;
    const int tid = threadIdx.x;
    const int tx  = tid & 15;
    const int ty  = tid >> 4;

    if (nb == 0) {
        if (tid < 64) {
            out_mask[tid * TT + t] = (t < lengths[tid]) ? 1.f : 0.f;
        } else if (tid == 64) {
            g_bar[t] = 0u;     // reset scan barrier for this launch (stream-ordered)
        }
    }

    if (tid < 64) {
        tok[tid] = inputs[tid * TT + t];
    } else if (tid < 128) {
        int n  = nb * 64 + (tid - 64);
        int wr = (n & 3) * 512 + (n >> 2);
        bias_s[tid - 64] = bih[wr] + bhh[wr];
    }
    __syncthreads();

    float acc[4][4] = {};
    for (int kc = 0; kc < EE; kc += 64) {
#pragma unroll
        for (int i = 0; i < 16; i++) {
            int idx = i * 256 + tid;
            int mi  = idx >> 6;
            int kk  = idx & 63;
            As[mi * 69 + kk] = emb[(size_t)tok[mi] * EE + kc + kk];
            int n  = nb * 64 + mi;
            int wr = (n & 3) * 512 + (n >> 2);
            Bs[mi * 69 + kk] = Wih[wr * EE + kc + kk];
        }
        __syncthreads();
#pragma unroll 8
        for (int kk = 0; kk < 64; kk++) {
            float a0 = As[(ty * 4 + 0) * 69 + kk];
            float a1 = As[(ty * 4 + 1) * 69 + kk];
            float a2 = As[(ty * 4 + 2) * 69 + kk];
            float a3 = As[(ty * 4 + 3) * 69 + kk];
            float b0 = Bs[(tx * 4 + 0) * 69 + kk];
            float b1 = Bs[(tx * 4 + 1) * 69 + kk];
            float b2 = Bs[(tx * 4 + 2) * 69 + kk];
            float b3 = Bs[(tx * 4 + 3) * 69 + kk];
            acc[0][0] = fmaf(a0, b0, acc[0][0]);
            acc[0][1] = fmaf(a0, b1, acc[0][1]);
            acc[0][2] = fmaf(a0, b2, acc[0][2]);
            acc[0][3] = fmaf(a0, b3, acc[0][3]);
            acc[1][0] = fmaf(a1, b0, acc[1][0]);
            acc[1][1] = fmaf(a1, b1, acc[1][1]);
            acc[1][2] = fmaf(a1, b2, acc[1][2]);
            acc[1][3] = fmaf(a1, b3, acc[1][3]);
            acc[2][0] = fmaf(a2, b0, acc[2][0]);
            acc[2][1] = fmaf(a2, b1, acc[2][1]);
            acc[2][2] = fmaf(a2, b2, acc[2][2]);
            acc[2][3] = fmaf(a2, b3, acc[2][3]);
            acc[3][0] = fmaf(a3, b0, acc[3][0]);
            acc[3][1] = fmaf(a3, b1, acc[3][1]);
            acc[3][2] = fmaf(a3, b2, acc[3][2]);
            acc[3][3] = fmaf(a3, b3, acc[3][3]);
        }
        __syncthreads();
    }

    float* gp = g_gates + (size_t)(t * 64) * G4 + nb * 64;
#pragma unroll
    for (int r = 0; r < 4; r++) {
        float4 v;
        v.x = acc[r][0] + bias_s[tx * 4 + 0];
        v.y = acc[r][1] + bias_s[tx * 4 + 1];
        v.z = acc[r][2] + bias_s[tx * 4 + 2];
        v.w = acc[r][3] + bias_s[tx * 4 + 3];
        *reinterpret_cast<float4*>(gp + (size_t)(ty * 4 + r) * G4 + tx * 4) = v;
    }
}

// ---------------- persistent LSTM scan -------------------------------------------
// 512 threads: pair = tid>>1 owns (b = pair>>2, jl = pair&3); half = tid&1 takes
// k-pairs p = 2q+half. Lane pairs reduce via shfl.xor(1). t=0 skips staging (h==0).
// Barrier (R5-proven): threadfence; syncthreads; tid0 relaxed atomicAdd; window
// work (d_out store + t+1 prefetch); tid0 volatile-poll with fixed nanosleep(64).
__global__ __launch_bounds__(512, 1) void scan_kernel(const float* __restrict__ Whh,
                                                      const int* __restrict__ lengths,
                                                      const int* __restrict__ resets,
                                                      float* __restrict__ d_out) {
    extern __shared__ float sm[];
    float* Wp = sm;                 // 256 p * 32 floats = 8192 floats (32 KB)
    float* hs = sm + 8192;          // 64 * 516 = 33024 floats (129 KB)

    const int tid  = threadIdx.x;
    const int pair = tid >> 1;     // 0..255
    const int half = tid & 1;      // 0 / 1  (k-parity split)
    const int b    = pair >> 2;    // 0..63
    const int jl   = pair & 3;     // 0..3
    const int j    = blockIdx.x * 4 + jl;

    // stage Wp: idx = p*32 + jl_*8 + g*2 + par -> Whh[(g*512 + j0+jl_)*512 + 2p+par]
    for (int idx = tid; idx < 8192; idx += 512) {
        int par = idx & 1;
        int g   = (idx >> 1) & 3;
        int jj  = (idx >> 3) & 3;
        int p   = idx >> 5;
        Wp[idx] = Whh[((size_t)(g * 512 + blockIdx.x * 4 + jj)) * 512 + 2 * p + par];
    }

    float c_reg = 0.f;
    const int len_b = lengths[b];

    const float4* gx4 = reinterpret_cast<const float4*>(g_gates);
    float* hT = d_out + (size_t)BB * TT * HH;
    float* cT = hT + BB * HH;

    const unsigned hs_s  = smem_u32(hs);
    const unsigned wp_s  = smem_u32(Wp);
    const unsigned hrow  = hs_s + (unsigned)(b * PH) * 4u;
    const unsigned wbase = wp_s + (unsigned)(jl * 8) * 4u;

    // prefetch step 0 operands
    float4 gx = __ldg(&gx4[(size_t)(0 * BB + b) * 512 + j]);
    int    rv = __ldg(&resets[b * TT + 0]);

    __syncthreads();

    for (int t = 0; t < TT; t++) {
        const float4* gh4 = reinterpret_cast<const float4*>(g_h[t & 1]);
        float*        ghw = g_h[(t + 1) & 1];

        unsigned long long acc0 = pk2(half ? 0.f : gx.x, 0.f);
        unsigned long long acc1 = pk2(half ? 0.f : gx.y, 0.f);
        unsigned long long acc2 = pk2(half ? 0.f : gx.z, 0.f);
        unsigned long long acc3 = pk2(half ? 0.f : gx.w, 0.f);

        float h_prev = 0.f;
        if (t > 0) {
            // ---- stage chunk 0 (k 0..127) ----
#pragma unroll
            for (int i = 0; i < 4; i++) {
                int idx = i * 512 + tid;           // 0..2047
                int b2  = idx >> 5;
                int q4  = idx & 31;
                float4 v = __ldcg(&gh4[b2 * 128 + q4]);
                sts_v4f32(hs_s + (unsigned)(b2 * PH + q4 * 4) * 4u, v);
            }
            __syncthreads();

#pragma unroll
            for (int c = 0; c < 4; c++) {
                if (c < 3) {
#pragma unroll
                    for (int i = 0; i < 4; i++) {
                        int idx = i * 512 + tid;
                        int b2  = idx >> 5;
                        int q4  = idx & 31;
                        float4 v = __ldcg(&gh4[b2 * 128 + (c + 1) * 32 + q4]);
                        sts_v4f32(hs_s + (unsigned)(b2 * PH + ((c + 1) * 32 + q4) * 4) * 4u, v);
                    }
                }
                // GEMV over q in [c*32, c*32+32), p = 2q + half
#pragma unroll 16
                for (int q = c * 32; q < c * 32 + 32; q++) {
                    int p = 2 * q + half;
                    unsigned long long h2 = lds_b64(hrow + (unsigned)(p * 8));
                    unsigned long long w0, w1, w2, w3;
                    unsigned wa = wbase + (unsigned)(p * 128);
                    lds_v2u64(wa,       w0, w1);
                    lds_v2u64(wa + 16u, w2, w3);
                    FFMA2(acc0, h2, w0);
                    FFMA2(acc1, h2, w1);
                    FFMA2(acc2, h2, w2);
                    FFMA2(acc3, h2, w3);
                }
                __syncthreads();
            }
            h_prev = hs[b * PH + j];
        }

        // ---- reduce: f32x2 halves, then lane-pair butterfly ----
        float2 r0 = upk2(acc0), r1 = upk2(acc1), r2 = upk2(acc2), r3 = upk2(acc3);
        float si = r0.x + r0.y;
        float sf = r1.x + r1.y;
        float sg = r2.x + r2.y;
        float so = r3.x + r3.y;
        si += __shfl_xor_sync(0xFFFFFFFFu, si, 1);
        sf += __shfl_xor_sync(0xFFFFFFFFu, sf, 1);
        sg += __shfl_xor_sync(0xFFFFFFFFu, sg, 1);
        so += __shfl_xor_sync(0xFFFFFFFFu, so, 1);

        float ig = 1.f / (1.f + __expf(-si));
        float fg = 1.f / (1.f + __expf(-sf));
        float gg = tanhf(sg);
        float og = 1.f / (1.f + __expf(-so));
        float c_new = fg * c_reg + ig * gg;
        float h_new = og * tanhf(c_new);

        float m  = (t < len_b) ? 1.f : 0.f;
        float h_nx = m * h_new + (1.f - m) * h_prev;
        float c_nx = m * c_new + (1.f - m) * c_reg;

        float rr = (float)rv;
        c_reg = c_nx * (1.f - rr);
        float h_carry = h_nx * (1.f - rr);
        if (half == 0) ghw[b * HH + j] = h_carry;    // publish BEFORE barrier

        if (t < TT - 1) {
            __threadfence();                          // publish to GPU scope
            __syncthreads();                          // whole CTA published
            if (tid == 0) atomicAdd(&g_bar[t], 1u);   // arrive (relaxed)

            // useful work inside the barrier window:
            if (half == 0) d_out[((size_t)b * TT + t) * HH + j] = h_nx;
            gx = __ldg(&gx4[(size_t)((t + 1) * BB + b) * 512 + j]);
            rv = __ldg(&resets[b * TT + t + 1]);

            if (tid == 0) {
                while (*((volatile unsigned*)&g_bar[t]) < (unsigned)NCTA) {
                    __nanosleep(64);
                }
            }
            __syncthreads();
        } else {
            if (half == 0) {
                d_out[((size_t)b * TT + t) * HH + j] = h_nx;
                hT[b * HH + j] = h_carry;
                cT[b * HH + j] = c_reg;
            }
        }
    }
}

// ---------------- launch ---------------------------------------------------------
extern "C" void kernel_launch(void* const* d_in, const int* in_sizes, int n_in,
                              void* d_out, int out_size) {
    const int*   inputs  = (const int*)d_in[0];
    const int*   lengths = (const int*)d_in[1];
    const int*   resets  = (const int*)d_in[2];
    const float* emb     = (const float*)d_in[3];
    const float* Wih     = (const float*)d_in[4];
    const float* Whh     = (const float*)d_in[5];
    const float* bih     = (const float*)d_in[6];
    const float* bhh     = (const float*)d_in[7];
    float* out = (float*)d_out;
    float* out_mask = out + (size_t)BB * TT * HH + 2 * (size_t)BB * HH;

    const int SMEM_SCAN = (8192 + 64 * PH) * (int)sizeof(float);  // 164864 B
    cudaFuncSetAttribute(scan_kernel, cudaFuncAttributeMaxDynamicSharedMemorySize, SMEM_SCAN);

    gates_kernel<<<dim3(32, 512), 256>>>(inputs, emb, Wih, bih, bhh, lengths, out_mask);
    scan_kernel<<<NCTA, 512, SMEM_SCAN>>>(Whh, lengths, resets, out);
}

// round 9
// speedup vs baseline: 1.5319x; 1.4901x over previous
#include <cuda_runtime.h>
#include <cstdint>

#define BB 64
#define TT 512
#define HH 512
#define EE 256
#define G4 2048          // 4*H
#define NCTA 128         // persistent CTAs in scan (<= 148 SMs, all co-resident)
#define PH  516          // hs row pitch in floats: 2064B = 16B-aligned, 516 mod 32 = 4

// ---------------- device scratch (static: no allocations allowed) ----------------
__device__ float    g_gates[(size_t)TT * BB * G4];  // 256 MB: gates_x, layout [t][b][j][gate]
__device__ float    g_h[2][BB * HH];                // double-buffered carry h (post-reset)
__device__ int      g_rT[TT * BB];                  // reset transposed [t][b]
__device__ unsigned g_bar[TT];                      // per-step barrier counters

// ---------------- small asm helpers ----------------------------------------------
__device__ __forceinline__ unsigned long long pk2(float lo, float hi) {
    unsigned long long r;
    asm("mov.b64 %0, {%1,%2};" : "=l"(r) : "f"(lo), "f"(hi));
    return r;
}
__device__ __forceinline__ float2 upk2(unsigned long long v) {
    float2 r;
    asm("mov.b64 {%0,%1}, %2;" : "=f"(r.x), "=f"(r.y) : "l"(v));
    return r;
}
#define FFMA2(acc, a, b) \
    asm("fma.rn.f32x2 %0, %1, %2, %0;" : "+l"(acc) : "l"(a), "l"(b))

__device__ __forceinline__ unsigned smem_u32(const void* p) {
    return (unsigned)__cvta_generic_to_shared(p);
}
__device__ __forceinline__ unsigned long long lds_b64(unsigned addr) {
    unsigned long long r;
    asm("ld.shared.b64 %0, [%1];" : "=l"(r) : "r"(addr));
    return r;
}
__device__ __forceinline__ void lds_v2u64(unsigned addr, unsigned long long& a,
                                          unsigned long long& b) {
    asm("ld.shared.v2.u64 {%0,%1}, [%2];" : "=l"(a), "=l"(b) : "r"(addr));
}
// cp.async.cg: global(L2) -> shared, 16B, bypassing the register file & L1 cache.
__device__ __forceinline__ void cp_async16(unsigned smem_dst, const void* gsrc) {
    asm volatile("cp.async.cg.shared.global [%0], [%1], 16;"
                 :: "r"(smem_dst), "l"(__cvta_generic_to_global(gsrc)) : "memory");
}
#define CP_COMMIT()  asm volatile("cp.async.commit_group;" ::: "memory")
#define CP_WAIT(n)   asm volatile("cp.async.wait_group " #n ";" ::: "memory")

// ---------------- init: zero state/barriers, build rT + mask output --------------
__global__ void init_kernel(const int* __restrict__ lengths,
                            const int* __restrict__ resets,
                            float* __restrict__ out_mask) {
    int idx = blockIdx.x * blockDim.x + threadIdx.x;   // 0..32767
    if (idx < TT) g_bar[idx] = 0u;
    if (idx < BB * HH) { g_h[0][idx] = 0.f; g_h[1][idx] = 0.f; }
    int b = idx >> 9;
    int t = idx & 511;
    int rv = resets[b * TT + t];
    g_rT[t * BB + b] = rv;
    out_mask[b * TT + t] = (t < lengths[b]) ? 1.f : 0.f;
}

// ---------------- gates_x GEMM with fused embedding gather (unchanged, proven) ---
__global__ __launch_bounds__(256) void gates_kernel(const int* __restrict__ inputs,
                                                    const float* __restrict__ emb,
                                                    const float* __restrict__ Wih,
                                                    const float* __restrict__ bih,
                                                    const float* __restrict__ bhh) {
    __shared__ float As[64 * 69];   // [b][k] pitch 69
    __shared__ float Bs[64 * 69];   // [n][k] pitch 69
    __shared__ int   tok[64];
    __shared__ float bias_s[64];

    const int t   = blockIdx.y;
    const int nb  = blockIdx.x;
    const int tid = threadIdx.x;
    const int tx  = tid & 15;
    const int ty  = tid >> 4;

    if (tid < 64) {
        tok[tid] = inputs[tid * TT + t];
    } else if (tid < 128) {
        int n  = nb * 64 + (tid - 64);
        int wr = (n & 3) * 512 + (n >> 2);
        bias_s[tid - 64] = bih[wr] + bhh[wr];
    }
    __syncthreads();

    float acc[4][4] = {};
    for (int kc = 0; kc < EE; kc += 64) {
#pragma unroll
        for (int i = 0; i < 16; i++) {
            int idx = i * 256 + tid;
            int mi  = idx >> 6;
            int kk  = idx & 63;
            As[mi * 69 + kk] = emb[(size_t)tok[mi] * EE + kc + kk];
            int n  = nb * 64 + mi;
            int wr = (n & 3) * 512 + (n >> 2);
            Bs[mi * 69 + kk] = Wih[wr * EE + kc + kk];
        }
        __syncthreads();
#pragma unroll 8
        for (int kk = 0; kk < 64; kk++) {
            float a0 = As[(ty * 4 + 0) * 69 + kk];
            float a1 = As[(ty * 4 + 1) * 69 + kk];
            float a2 = As[(ty * 4 + 2) * 69 + kk];
            float a3 = As[(ty * 4 + 3) * 69 + kk];
            float b0 = Bs[(tx * 4 + 0) * 69 + kk];
            float b1 = Bs[(tx * 4 + 1) * 69 + kk];
            float b2 = Bs[(tx * 4 + 2) * 69 + kk];
            float b3 = Bs[(tx * 4 + 3) * 69 + kk];
            acc[0][0] = fmaf(a0, b0, acc[0][0]);
            acc[0][1] = fmaf(a0, b1, acc[0][1]);
            acc[0][2] = fmaf(a0, b2, acc[0][2]);
            acc[0][3] = fmaf(a0, b3, acc[0][3]);
            acc[1][0] = fmaf(a1, b0, acc[1][0]);
            acc[1][1] = fmaf(a1, b1, acc[1][1]);
            acc[1][2] = fmaf(a1, b2, acc[1][2]);
            acc[1][3] = fmaf(a1, b3, acc[1][3]);
            acc[2][0] = fmaf(a2, b0, acc[2][0]);
            acc[2][1] = fmaf(a2, b1, acc[2][1]);
            acc[2][2] = fmaf(a2, b2, acc[2][2]);
            acc[2][3] = fmaf(a2, b3, acc[2][3]);
            acc[3][0] = fmaf(a3, b0, acc[3][0]);
            acc[3][1] = fmaf(a3, b1, acc[3][1]);
            acc[3][2] = fmaf(a3, b2, acc[3][2]);
            acc[3][3] = fmaf(a3, b3, acc[3][3]);
        }
        __syncthreads();
    }

    float* gp = g_gates + (size_t)(t * 64) * G4 + nb * 64;
#pragma unroll
    for (int r = 0; r < 4; r++) {
        float4 v;
        v.x = acc[r][0] + bias_s[tx * 4 + 0];
        v.y = acc[r][1] + bias_s[tx * 4 + 1];
        v.z = acc[r][2] + bias_s[tx * 4 + 2];
        v.w = acc[r][3] + bias_s[tx * 4 + 3];
        *reinterpret_cast<float4*>(gp + (size_t)(ty * 4 + r) * G4 + tx * 4) = v;
    }
}

// ---------------- persistent LSTM scan (R5 structure + cp.async deep staging) ----
// CTA owns j in [cta*4, cta*4+4). Thread: b = tid>>2, jl = tid&3. 256 threads.
// Staging: all 4 k-chunks of h (128 KB) issued at step start as 4 cp.async.cg
// commit-groups (L2-coherent, no register round-trip); each chunk drained with
// wait_group just before its GEMV slice -> 4-deep latency pipeline.
__global__ __launch_bounds__(256, 1) void scan_kernel(const float* __restrict__ Whh,
                                                      const int* __restrict__ lengths,
                                                      float* __restrict__ d_out) {
    extern __shared__ float sm[];
    float* Wp = sm;                 // 256*4*4*2 = 8192 floats (32 KB)
    float* hs = sm + 8192;          // 64 * 516  = 33024 floats (129 KB)

    const int tid = threadIdx.x;
    const int b   = tid >> 2;      // 0..63
    const int jl  = tid & 3;       // 0..3
    const int j   = blockIdx.x * 4 + jl;

    // stage Wp: idx = p*32 + jl_*8 + g*2 + par -> Whh[(g*512 + j0+jl_)*512 + 2p+par]
    for (int idx = tid; idx < 8192; idx += 256) {
        int par = idx & 1;
        int g   = (idx >> 1) & 3;
        int jj  = (idx >> 3) & 3;
        int p   = idx >> 5;
        Wp[idx] = Whh[((size_t)(g * 512 + blockIdx.x * 4 + jj)) * 512 + 2 * p + par];
    }

    float c_reg = 0.f;
    const int len_b = lengths[b];

    const float4* gx4 = reinterpret_cast<const float4*>(g_gates);
    float* hT = d_out + (size_t)BB * TT * HH;
    float* cT = hT + BB * HH;

    const unsigned hs_s  = smem_u32(hs);
    const unsigned wp_s  = smem_u32(Wp);
    const unsigned hrow  = hs_s + (unsigned)(b * PH) * 4u;
    const unsigned wbase = wp_s + (unsigned)(jl * 8) * 4u;

    __syncthreads();

    for (int t = 0; t < TT; t++) {
        const float4* gh4 = reinterpret_cast<const float4*>(g_h[t & 1]);
        float*        ghw = g_h[(t + 1) & 1];

        // gx prefetch (DRAM) overlaps the async staging below
        float4 gx = __ldg(&gx4[(size_t)(t * BB + b) * 512 + j]);

        // ---- issue ALL h staging up front: 4 chunks = 4 commit groups ----
#pragma unroll
        for (int c2 = 0; c2 < 4; c2++) {
#pragma unroll
            for (int i = 0; i < 8; i++) {
                int idx = i * 256 + tid;       // 0..2047
                int b2  = idx >> 5;            // batch row
                int q4  = idx & 31;            // float4 within chunk
                cp_async16(hs_s + (unsigned)(b2 * PH + (c2 * 32 + q4) * 4) * 4u,
                           &gh4[b2 * 128 + c2 * 32 + q4]);
            }
            CP_COMMIT();
        }

        unsigned long long acc0 = pk2(gx.x, 0.f);
        unsigned long long acc1 = pk2(gx.y, 0.f);
        unsigned long long acc2 = pk2(gx.z, 0.f);
        unsigned long long acc3 = pk2(gx.w, 0.f);

        // ---- 4-deep pipelined consume: wait chunk c, sync, GEMV chunk c ----
#pragma unroll
        for (int c = 0; c < 4; c++) {
            if      (c == 0) CP_WAIT(3);
            else if (c == 1) CP_WAIT(2);
            else if (c == 2) CP_WAIT(1);
            else             CP_WAIT(0);
            __syncthreads();
#pragma unroll 16
            for (int p = c * 64; p < c * 64 + 64; p++) {
                unsigned long long h2 = lds_b64(hrow + (unsigned)(2 * p) * 4u);
                unsigned long long w0, w1, w2, w3;
                unsigned wa = wbase + (unsigned)(p * 32) * 4u;
                lds_v2u64(wa,       w0, w1);
                lds_v2u64(wa + 16u, w2, w3);
                FFMA2(acc0, h2, w0);
                FFMA2(acc1, h2, w1);
                FFMA2(acc2, h2, w2);
                FFMA2(acc3, h2, w3);
            }
        }
        float h_prev = hs[b * PH + j];

        // ---- reduce f32x2 halves, activations, state update ----
        float2 r0 = upk2(acc0), r1 = upk2(acc1), r2 = upk2(acc2), r3 = upk2(acc3);
        float si = r0.x + r0.y;
        float sf = r1.x + r1.y;
        float sg = r2.x + r2.y;
        float so = r3.x + r3.y;

        float ig = 1.f / (1.f + __expf(-si));
        float fg = 1.f / (1.f + __expf(-sf));
        float gg = tanhf(sg);
        float og = 1.f / (1.f + __expf(-so));
        float c_new = fg * c_reg + ig * gg;
        float h_new = og * tanhf(c_new);

        float m  = (t < len_b) ? 1.f : 0.f;
        float h_nx = m * h_new + (1.f - m) * h_prev;
        float c_nx = m * c_new + (1.f - m) * c_reg;

        d_out[((size_t)b * TT + t) * HH + j] = h_nx;

        float rr = (float)g_rT[t * BB + b];
        c_reg = c_nx * (1.f - rr);
        float h_carry = h_nx * (1.f - rr);
        ghw[b * HH + j] = h_carry;

        if (t == TT - 1) {
            hT[b * HH + j] = h_carry;
            cT[b * HH + j] = c_reg;
        }

        // ---- grid barrier (R5-proven): fence, sync, tid0 arrive+poll, sync ----
        __threadfence();
        __syncthreads();
        if (t < TT - 1) {
            if (tid == 0) {
                unsigned arrived = atomicAdd(&g_bar[t], 1u) + 1u;
                if (arrived < (unsigned)NCTA) {
                    while (*((volatile unsigned*)&g_bar[t]) < (unsigned)NCTA) {
                        __nanosleep(64);
                    }
                }
            }
            __syncthreads();
        }
    }
}

// ---------------- launch ---------------------------------------------------------
extern "C" void kernel_launch(void* const* d_in, const int* in_sizes, int n_in,
                              void* d_out, int out_size) {
    const int*   inputs  = (const int*)d_in[0];
    const int*   lengths = (const int*)d_in[1];
    const int*   resets  = (const int*)d_in[2];
    const float* emb     = (const float*)d_in[3];
    const float* Wih     = (const float*)d_in[4];
    const float* Whh     = (const float*)d_in[5];
    const float* bih     = (const float*)d_in[6];
    const float* bhh     = (const float*)d_in[7];
    float* out = (float*)d_out;
    float* out_mask = out + (size_t)BB * TT * HH + 2 * (size_t)BB * HH;

    const int SMEM_SCAN = (8192 + 64 * PH) * (int)sizeof(float);  // 164864 B
    cudaFuncSetAttribute(scan_kernel, cudaFuncAttributeMaxDynamicSharedMemorySize, SMEM_SCAN);

    init_kernel<<<128, 256>>>(lengths, resets, out_mask);
    gates_kernel<<<dim3(32, 512), 256>>>(inputs, emb, Wih, bih, bhh);
    scan_kernel<<<NCTA, 256, SMEM_SCAN>>>(Whh, lengths, out);
}

// round 13
// speedup vs baseline: 2.1170x; 1.3819x over previous
#include <cuda_runtime.h>
#include <cstdint>

#define BB 64
#define TT 512
#define HH 512
#define EE 256
#define G4 2048          // 4*H
#define NGRP 4           // independent batch groups
#define NCTAH 32         // hidden-partition CTAs per group
#define BG 16            // batches per group
#define JU 16            // hidden units per CTA
#define PH  516          // hs row pitch in floats (2064B, 16B-aligned, 4 mod 32)

// ---------------- device scratch (static: no allocations allowed) ----------------
__device__ float    g_gates[(size_t)TT * BB * G4];  // gates_x [t][b][j][gate]
__device__ float    g_h[2][BB * HH];                // double-buffered carry h [b][k]
__device__ int      g_rT[TT * BB];                  // reset transposed [t][b]
__device__ unsigned g_bar[NGRP * TT];               // per-(group,step) barrier counters

// ---------------- small asm helpers ----------------------------------------------
__device__ __forceinline__ unsigned long long pk2(float lo, float hi) {
    unsigned long long r;
    asm("mov.b64 %0, {%1,%2};" : "=l"(r) : "f"(lo), "f"(hi));
    return r;
}
__device__ __forceinline__ float2 upk2(unsigned long long v) {
    float2 r;
    asm("mov.b64 {%0,%1}, %2;" : "=f"(r.x), "=f"(r.y) : "l"(v));
    return r;
}
#define FFMA2(acc, a, b) \
    asm("fma.rn.f32x2 %0, %1, %2, %0;" : "+l"(acc) : "l"(a), "l"(b))

__device__ __forceinline__ unsigned smem_u32(const void* p) {
    return (unsigned)__cvta_generic_to_shared(p);
}
__device__ __forceinline__ unsigned long long lds_b64(unsigned addr) {
    unsigned long long r;
    asm("ld.shared.b64 %0, [%1];" : "=l"(r) : "r"(addr));
    return r;
}
__device__ __forceinline__ void lds_v2u64(unsigned addr, unsigned long long& a,
                                          unsigned long long& b) {
    asm("ld.shared.v2.u64 {%0,%1}, [%2];" : "=l"(a), "=l"(b) : "r"(addr));
}
// cp.async.cg: global(L2) -> shared, 16B, no register round-trip.
__device__ __forceinline__ void cp_async16(unsigned smem_dst, const void* gsrc) {
    asm volatile("cp.async.cg.shared.global [%0], [%1], 16;"
                 :: "r"(smem_dst), "l"(__cvta_generic_to_global(gsrc)) : "memory");
}
#define CP_COMMIT()  asm volatile("cp.async.commit_group;" ::: "memory")
#define CP_WAIT(n)   asm volatile("cp.async.wait_group " #n ";" ::: "memory")

// ---------------- init: zero state/barriers, build rT + mask output --------------
__global__ void init_kernel(const int* __restrict__ lengths,
                            const int* __restrict__ resets,
                            float* __restrict__ out_mask) {
    int idx = blockIdx.x * blockDim.x + threadIdx.x;   // 0..32767
    if (idx < NGRP * TT) g_bar[idx] = 0u;
    if (idx < BB * HH) { g_h[0][idx] = 0.f; g_h[1][idx] = 0.f; }
    int b = idx >> 9;
    int t = idx & 511;
    int rv = resets[b * TT + t];
    g_rT[t * BB + b] = rv;
    out_mask[b * TT + t] = (t < lengths[b]) ? 1.f : 0.f;
}

// ---------------- gates_x GEMM with fused embedding gather (unchanged, proven) ---
__global__ __launch_bounds__(256) void gates_kernel(const int* __restrict__ inputs,
                                                    const float* __restrict__ emb,
                                                    const float* __restrict__ Wih,
                                                    const float* __restrict__ bih,
                                                    const float* __restrict__ bhh) {
    __shared__ float As[64 * 69];
    __shared__ float Bs[64 * 69];
    __shared__ int   tok[64];
    __shared__ float bias_s[64];

    const int t   = blockIdx.y;
    const int nb  = blockIdx.x;
    const int tid = threadIdx.x;
    const int tx  = tid & 15;
    const int ty  = tid >> 4;

    if (tid < 64) {
        tok[tid] = inputs[tid * TT + t];
    } else if (tid < 128) {
        int n  = nb * 64 + (tid - 64);
        int wr = (n & 3) * 512 + (n >> 2);
        bias_s[tid - 64] = bih[wr] + bhh[wr];
    }
    __syncthreads();

    float acc[4][4] = {};
    for (int kc = 0; kc < EE; kc += 64) {
#pragma unroll
        for (int i = 0; i < 16; i++) {
            int idx = i * 256 + tid;
            int mi  = idx >> 6;
            int kk  = idx & 63;
            As[mi * 69 + kk] = emb[(size_t)tok[mi] * EE + kc + kk];
            int n  = nb * 64 + mi;
            int wr = (n & 3) * 512 + (n >> 2);
            Bs[mi * 69 + kk] = Wih[wr * EE + kc + kk];
        }
        __syncthreads();
#pragma unroll 8
        for (int kk = 0; kk < 64; kk++) {
            float a0 = As[(ty * 4 + 0) * 69 + kk];
            float a1 = As[(ty * 4 + 1) * 69 + kk];
            float a2 = As[(ty * 4 + 2) * 69 + kk];
            float a3 = As[(ty * 4 + 3) * 69 + kk];
            float b0 = Bs[(tx * 4 + 0) * 69 + kk];
            float b1 = Bs[(tx * 4 + 1) * 69 + kk];
            float b2 = Bs[(tx * 4 + 2) * 69 + kk];
            float b3 = Bs[(tx * 4 + 3) * 69 + kk];
            acc[0][0] = fmaf(a0, b0, acc[0][0]);
            acc[0][1] = fmaf(a0, b1, acc[0][1]);
            acc[0][2] = fmaf(a0, b2, acc[0][2]);
            acc[0][3] = fmaf(a0, b3, acc[0][3]);
            acc[1][0] = fmaf(a1, b0, acc[1][0]);
            acc[1][1] = fmaf(a1, b1, acc[1][1]);
            acc[1][2] = fmaf(a1, b2, acc[1][2]);
            acc[1][3] = fmaf(a1, b3, acc[1][3]);
            acc[2][0] = fmaf(a2, b0, acc[2][0]);
            acc[2][1] = fmaf(a2, b1, acc[2][1]);
            acc[2][2] = fmaf(a2, b2, acc[2][2]);
            acc[2][3] = fmaf(a2, b3, acc[2][3]);
            acc[3][0] = fmaf(a3, b0, acc[3][0]);
            acc[3][1] = fmaf(a3, b1, acc[3][1]);
            acc[3][2] = fmaf(a3, b2, acc[3][2]);
            acc[3][3] = fmaf(a3, b3, acc[3][3]);
        }
        __syncthreads();
    }

    float* gp = g_gates + (size_t)(t * 64) * G4 + nb * 64;
#pragma unroll
    for (int r = 0; r < 4; r++) {
        float4 v;
        v.x = acc[r][0] + bias_s[tx * 4 + 0];
        v.y = acc[r][1] + bias_s[tx * 4 + 1];
        v.z = acc[r][2] + bias_s[tx * 4 + 2];
        v.w = acc[r][3] + bias_s[tx * 4 + 3];
        *reinterpret_cast<float4*>(gp + (size_t)(ty * 4 + r) * G4 + tx * 4) = v;
    }
}

// ---------------- persistent LSTM scan: 4 independent groups x 32 CTAs -----------
// CTA (grp = blockIdx.x>>5, ch = blockIdx.x&31) owns batches [grp*16,grp*16+16)
// and hidden units [ch*16, ch*16+16). Thread: jl = tid>>4 (unit), bl = tid&15.
// Wp: 64 rows x 512 pair-packed = 128 KB SMEM (staged once). hs: group h slice,
// [bl][k] pitch 516 = 33 KB, staged per step via cp.async 4-deep pipeline.
// Barrier: per-group 32-CTA counter (R5-proven fence/arrive/poll pattern).
__global__ __launch_bounds__(256, 1) void scan_kernel(const float* __restrict__ Whh,
                                                      const int* __restrict__ lengths,
                                                      float* __restrict__ d_out) {
    extern __shared__ float sm[];
    float* Wp = sm;                 // 256 p * 128 floats = 32768 floats (128 KB)
    float* hs = sm + 32768;         // 16 * 516 = 8256 floats (33 KB)

    const int tid = threadIdx.x;
    const int jl  = tid >> 4;      // 0..15  unit within CTA
    const int bl  = tid & 15;      // 0..15  batch within group
    const int grp = blockIdx.x >> 5;
    const int ch  = blockIdx.x & 31;
    const int j   = ch * JU + jl;
    const int b   = grp * BG + bl;

    // stage Wp: idx = p*128 + jl_*8 + g*2 + par -> Whh[(g*512 + ch*16+jl_)*512 + 2p+par]
    for (int idx = tid; idx < 32768; idx += 256) {
        int par = idx & 1;
        int g   = (idx >> 1) & 3;
        int jj  = (idx >> 3) & 15;
        int p   = idx >> 7;
        Wp[idx] = Whh[((size_t)(g * 512 + ch * JU + jj)) * 512 + 2 * p + par];
    }

    float c_reg = 0.f;
    const int len_b = lengths[b];

    const float4* gx4 = reinterpret_cast<const float4*>(g_gates);
    float* hT = d_out + (size_t)BB * TT * HH;
    float* cT = hT + BB * HH;

    const unsigned hs_s  = smem_u32(hs);
    const unsigned wp_s  = smem_u32(Wp);
    const unsigned hrow  = hs_s + (unsigned)(bl * PH) * 4u;   // hs[bl][0]
    const unsigned wbase = wp_s + (unsigned)(jl * 8) * 4u;    // Wp[0][jl][0][0]
    unsigned* bar = &g_bar[grp * TT];

    __syncthreads();

    for (int t = 0; t < TT; t++) {
        const float4* gh4 = reinterpret_cast<const float4*>(g_h[t & 1]);
        float*        ghw = g_h[(t + 1) & 1];

        // gx prefetch (DRAM) overlaps the async staging below
        float4 gx = __ldg(&gx4[(size_t)(t * BB + b) * 512 + j]);

        // ---- issue group's h staging up front: 4 k-chunks = 4 commit groups ----
        // chunk c: float4 q4 in [c*32, c*32+32) for each of 16 local batches
#pragma unroll
        for (int c2 = 0; c2 < 4; c2++) {
#pragma unroll
            for (int i = 0; i < 2; i++) {
                int idx = i * 256 + tid;       // 0..511
                int b2  = idx >> 5;            // local batch 0..15
                int q4  = idx & 31;
                cp_async16(hs_s + (unsigned)(b2 * PH + (c2 * 32 + q4) * 4) * 4u,
                           &gh4[(grp * BG + b2) * 128 + c2 * 32 + q4]);
            }
            CP_COMMIT();
        }

        unsigned long long acc0 = pk2(gx.x, 0.f);
        unsigned long long acc1 = pk2(gx.y, 0.f);
        unsigned long long acc2 = pk2(gx.z, 0.f);
        unsigned long long acc3 = pk2(gx.w, 0.f);

        // ---- 4-deep pipelined consume ----
#pragma unroll
        for (int c = 0; c < 4; c++) {
            if      (c == 0) CP_WAIT(3);
            else if (c == 1) CP_WAIT(2);
            else if (c == 2) CP_WAIT(1);
            else             CP_WAIT(0);
            __syncthreads();
#pragma unroll 16
            for (int p = c * 64; p < c * 64 + 64; p++) {
                unsigned long long h2 = lds_b64(hrow + (unsigned)(2 * p) * 4u);
                unsigned long long w0, w1, w2, w3;
                unsigned wa = wbase + (unsigned)(p * 128) * 4u;
                lds_v2u64(wa,       w0, w1);
                lds_v2u64(wa + 16u, w2, w3);
                FFMA2(acc0, h2, w0);
                FFMA2(acc1, h2, w1);
                FFMA2(acc2, h2, w2);
                FFMA2(acc3, h2, w3);
            }
        }
        float h_prev = hs[bl * PH + j];

        // ---- reduce f32x2 halves, activations, state update ----
        float2 r0 = upk2(acc0), r1 = upk2(acc1), r2 = upk2(acc2), r3 = upk2(acc3);
        float si = r0.x + r0.y;
        float sf = r1.x + r1.y;
        float sg = r2.x + r2.y;
        float so = r3.x + r3.y;

        float ig = 1.f / (1.f + __expf(-si));
        float fg = 1.f / (1.f + __expf(-sf));
        float gg = tanhf(sg);
        float og = 1.f / (1.f + __expf(-so));
        float c_new = fg * c_reg + ig * gg;
        float h_new = og * tanhf(c_new);

        float m  = (t < len_b) ? 1.f : 0.f;
        float h_nx = m * h_new + (1.f - m) * h_prev;
        float c_nx = m * c_new + (1.f - m) * c_reg;

        d_out[((size_t)b * TT + t) * HH + j] = h_nx;

        float rr = (float)g_rT[t * BB + b];
        c_reg = c_nx * (1.f - rr);
        float h_carry = h_nx * (1.f - rr);
        ghw[b * HH + j] = h_carry;

        if (t == TT - 1) {
            hT[b * HH + j] = h_carry;
            cT[b * HH + j] = c_reg;
        }

        // ---- per-group grid barrier (32 CTAs): fence, sync, arrive+poll, sync ----
        __threadfence();
        __syncthreads();
        if (t < TT - 1) {
            if (tid == 0) {
                unsigned arrived = atomicAdd(&bar[t], 1u) + 1u;
                if (arrived < (unsigned)NCTAH) {
                    while (*((volatile unsigned*)&bar[t]) < (unsigned)NCTAH) {
                        __nanosleep(64);
                    }
                }
            }
            __syncthreads();
        }
    }
}

// ---------------- launch ---------------------------------------------------------
extern "C" void kernel_launch(void* const* d_in, const int* in_sizes, int n_in,
                              void* d_out, int out_size) {
    const int*   inputs  = (const int*)d_in[0];
    const int*   lengths = (const int*)d_in[1];
    const int*   resets  = (const int*)d_in[2];
    const float* emb     = (const float*)d_in[3];
    const float* Wih     = (const float*)d_in[4];
    const float* Whh     = (const float*)d_in[5];
    const float* bih     = (const float*)d_in[6];
    const float* bhh     = (const float*)d_in[7];
    float* out = (float*)d_out;
    float* out_mask = out + (size_t)BB * TT * HH + 2 * (size_t)BB * HH;

    const int SMEM_SCAN = (32768 + BG * PH) * (int)sizeof(float);  // 164096 B
    cudaFuncSetAttribute(scan_kernel, cudaFuncAttributeMaxDynamicSharedMemorySize, SMEM_SCAN);

    init_kernel<<<128, 256>>>(lengths, resets, out_mask);
    gates_kernel<<<dim3(32, 512), 256>>>(inputs, emb, Wih, bih, bhh);
    scan_kernel<<<NGRP * NCTAH, 256, SMEM_SCAN>>>(Whh, lengths, out);
}